// round 14
// baseline (speedup 1.0000x reference)
#include <cuda_runtime.h>
#include <cuda_fp16.h>
#include <cstdint>

#define T_STEPS 256
#define BSZ     25
#define VOCAB   32000
#define HID     1024
#define NCLS    2
#define MROWS   6400
#define NBLK_RECUR 128
#define KT      1000           // k-tiles of 32 (32000/32)
#define KSPLIT  2
#define KT_HALF 500
#define TILEB   8192           // bytes per packed tile (128 rows x 32 k x fp16)

// ---------------- device scratch ----------------
__device__ float g_Z[MROWS * HID];                        // 26 MB (k-split 0)
__device__ float g_Z2[MROWS * HID];                       // 26 MB (k-split 1)
__device__ float g_WhhT[HID * HID];                       // 4 MB
__device__ float g_h[2][BSZ * HID];
__device__ __align__(256) uint8_t g_Apk[(size_t)50 * KT * TILEB];  // 409.6 MB
__device__ __align__(256) uint8_t g_Bpk[(size_t)8  * KT * TILEB];  // 65.5 MB
__device__ int   g_flags[NBLK_RECUR * 32];
__device__ volatile int g_rel;

// ---------------- helpers ----------------
__device__ __forceinline__ uint32_t s2u(const void* p) {
    uint32_t a;
    asm("{ .reg .u64 t; cvta.to.shared.u64 t, %1; cvt.u32.u64 %0, t; }" : "=r"(a) : "l"(p));
    return a;
}
__device__ __forceinline__ void mbar_init(uint32_t m, uint32_t c) {
    asm volatile("mbarrier.init.shared.b64 [%0], %1;" :: "r"(m), "r"(c) : "memory");
}
__device__ __forceinline__ void mbar_expect(uint32_t m, uint32_t bytes) {
    asm volatile("mbarrier.arrive.expect_tx.shared.b64 _, [%0], %1;" :: "r"(m), "r"(bytes) : "memory");
}
__device__ __forceinline__ void mbar_wait(uint32_t m, uint32_t ph) {
    asm volatile(
        "{\n\t.reg .pred P;\n\t"
        "W%=:\n\t"
        "mbarrier.try_wait.parity.acquire.cta.shared::cta.b64 P, [%0], %1, 0x989680;\n\t"
        "@P bra.uni D%=;\n\t"
        "bra.uni W%=;\n\t"
        "D%=:\n\t}" :: "r"(m), "r"(ph) : "memory");
}
__device__ __forceinline__ void bulk_g2s(uint32_t dst, const void* src, uint32_t bytes, uint32_t mbar) {
    asm volatile(
        "cp.async.bulk.shared::cluster.global.mbarrier::complete_tx::bytes [%0], [%1], %2, [%3];"
        :: "r"(dst), "l"(src), "r"(bytes), "r"(mbar) : "memory");
}
// fp16-accumulate HMMA: D = A*B (zero C)
__device__ __forceinline__ void hmma16_z(uint32_t* d, uint32_t a0, uint32_t a1, uint32_t a2,
                                         uint32_t a3, uint32_t b0, uint32_t b1) {
    asm volatile(
        "mma.sync.aligned.m16n8k16.row.col.f16.f16.f16.f16 "
        "{%0,%1}, {%2,%3,%4,%5}, {%6,%7}, {%8,%8};\n"
        : "=r"(d[0]), "=r"(d[1])
        : "r"(a0), "r"(a1), "r"(a2), "r"(a3), "r"(b0), "r"(b1), "r"(0u));
}
// fp16-accumulate HMMA: D += A*B
__device__ __forceinline__ void hmma16(uint32_t* d, uint32_t a0, uint32_t a1, uint32_t a2,
                                       uint32_t a3, uint32_t b0, uint32_t b1) {
    asm volatile(
        "mma.sync.aligned.m16n8k16.row.col.f16.f16.f16.f16 "
        "{%0,%1}, {%2,%3,%4,%5}, {%6,%7}, {%0,%1};\n"
        : "+r"(d[0]), "+r"(d[1])
        : "r"(a0), "r"(a1), "r"(a2), "r"(a3), "r"(b0), "r"(b1));
}

// packed in-row byte offset for k-pair p within a 32-k row (fragment-ordered)
__device__ __forceinline__ uint32_t koff_pair(int p) {
    return (uint32_t)((p & 3) * 16 + (p >> 2) * 4);
}

// ---------------- init ----------------
__global__ void init_k() {
    int tid = blockIdx.x * 256 + threadIdx.x;
    if (tid == 0) g_rel = 0;
    if (tid < NBLK_RECUR * 32) g_flags[tid] = 0;
    if (tid < BSZ * HID) g_h[0][tid] = 0.0f;
}

// ---------------- W_hh transpose ----------------
__global__ void transpose_k(const float* __restrict__ W) {
    __shared__ float tile[32][33];
    int x = blockIdx.x * 32 + threadIdx.x;
    int y = blockIdx.y * 32 + threadIdx.y;
    #pragma unroll
    for (int i = 0; i < 32; i += 8)
        tile[threadIdx.y + i][threadIdx.x] = W[(y + i) * HID + x];
    __syncthreads();
    x = blockIdx.y * 32 + threadIdx.x;
    y = blockIdx.x * 32 + threadIdx.y;
    #pragma unroll
    for (int i = 0; i < 32; i += 8)
        g_WhhT[(y + i) * HID + x] = tile[threadIdx.x][threadIdx.y + i];
}

// ---------------- pack_all: A (y<50) and B (y>=50) fp16 fragment-ordered tiles ----------------
__global__ void __launch_bounds__(256) pack_all(const float* __restrict__ X,
                                                const float* __restrict__ Wxh) {
    const int kt = blockIdx.x;
    const int y  = blockIdx.y;
    if (y < 50) {
        uint8_t* dst = g_Apk + ((size_t)y * KT + kt) * TILEB;
        const float* src = X + (size_t)(y * 128) * VOCAB + kt * 32;
        #pragma unroll
        for (int i = 0; i < 8; i++) {
            int idx = threadIdx.x + i * 256;
            int m = idx >> 4, p = idx & 15;
            float2 v = *(const float2*)&src[(size_t)m * VOCAB + p * 2];
            __half2 h = __floats2half2_rn(v.x, v.y);
            *(uint32_t*)(dst + m * 64 + koff_pair(p)) = *(uint32_t*)&h;
        }
    } else {
        __shared__ float s[32][132];
        const int nb = y - 50;
        uint8_t* dst = g_Bpk + ((size_t)nb * KT + kt) * TILEB;
        #pragma unroll
        for (int i = 0; i < 16; i++) {
            int idx = threadIdx.x + i * 256;
            int kk = idx >> 7, n = idx & 127;
            s[kk][n] = Wxh[(size_t)(kt * 32 + kk) * HID + nb * 128 + n];
        }
        __syncthreads();
        #pragma unroll
        for (int i = 0; i < 8; i++) {
            int idx = threadIdx.x + i * 256;
            int n = idx >> 4, p = idx & 15;
            __half2 h = __floats2half2_rn(s[2 * p][n], s[2 * p + 1][n]);
            *(uint32_t*)(dst + n * 64 + koff_pair(p)) = *(uint32_t*)&h;
        }
    }
}

// ---------------- Phase 1: Z = X @ W_xh  (fp16-ACCUMULATE mma.sync, split-K=2) ----------------
// grid (8 nb, 50 mb, 2 kz), 256 threads = 8 warps (4m x 2n), warp tile 32x64.
// BK=32 chunks accumulated in fp16 (2x HMMA rate), promoted to fp32 each iter.
__global__ void __launch_bounds__(256) gemm_fp16() {
    __shared__ __align__(128) uint8_t sA[2][TILEB];
    __shared__ __align__(128) uint8_t sB[2][TILEB];
    __shared__ __align__(8) uint64_t s_full[2];

    const int tid  = threadIdx.x;
    const int lane = tid & 31;
    const int warp = tid >> 5;
    const int wm   = warp & 3;
    const int wn   = warp >> 2;
    const int g    = lane >> 2;
    const int tg   = lane & 3;
    const int nb   = blockIdx.x, mb = blockIdx.y, kz = blockIdx.z;
    const int kt0  = kz * KT_HALF;

    const uint32_t mb_full[2] = { s2u(&s_full[0]), s2u(&s_full[1]) };
    if (tid == 0) { mbar_init(mb_full[0], 1); mbar_init(mb_full[1], 1); }
    __syncthreads();

    const uint8_t* Ab = g_Apk + (size_t)mb * KT * TILEB;
    const uint8_t* Bb = g_Bpk + (size_t)nb * KT * TILEB;
    const uint32_t sa0 = s2u(&sA[0][0]), sb0 = s2u(&sB[0][0]);

    if (tid == 0) {
        #pragma unroll
        for (int s = 0; s < 2; s++) {
            mbar_expect(mb_full[s], 2 * TILEB);
            bulk_g2s(sa0 + s * TILEB, Ab + (size_t)(kt0 + s) * TILEB, TILEB, mb_full[s]);
            bulk_g2s(sb0 + s * TILEB, Bb + (size_t)(kt0 + s) * TILEB, TILEB, mb_full[s]);
        }
    }

    float acc[2][8][4];
    #pragma unroll
    for (int mi = 0; mi < 2; mi++)
        #pragma unroll
        for (int ni = 0; ni < 8; ni++)
            #pragma unroll
            for (int j = 0; j < 4; j++) acc[mi][ni][j] = 0.0f;

    const uint32_t a_off = (uint32_t)((wm * 32 + g) * 64 + tg * 16);
    const uint32_t b_off = (uint32_t)((wn * 64 + g) * 64 + tg * 16);

    #pragma unroll 1
    for (int it = 0; it < KT_HALF; it++) {
        const int s  = it & 1;
        const int ph = (it >> 1) & 1;
        mbar_wait(mb_full[s], ph);

        const uint8_t* As = sA[s];
        const uint8_t* Bs = sB[s];

        uint4 aL0 = *(const uint4*)(As + a_off);
        uint4 aH0 = *(const uint4*)(As + a_off + 512);
        uint4 aL1 = *(const uint4*)(As + a_off + 1024);
        uint4 aH1 = *(const uint4*)(As + a_off + 1536);
        uint4 bf[8];
        #pragma unroll
        for (int ni = 0; ni < 8; ni++)
            bf[ni] = *(const uint4*)(Bs + b_off + ni * 512);

        // stage free once all threads hold their regs -> refill BEFORE compute
        __syncthreads();
        const int nk = it + 2;
        if (tid == 0 && nk < KT_HALF) {
            mbar_expect(mb_full[s], 2 * TILEB);
            bulk_g2s(sa0 + s * TILEB, Ab + (size_t)(kt0 + nk) * TILEB, TILEB, mb_full[s]);
            bulk_g2s(sb0 + s * TILEB, Bb + (size_t)(kt0 + nk) * TILEB, TILEB, mb_full[s]);
        }

        // fp16-accumulate chunk: pass1 = 16 independent zero-start HMMAs (k0..15),
        // pass2 = 16 chained HMMAs (k16..31). RAW distance 16.
        uint32_t hh[2][8][2];
        #pragma unroll
        for (int ni = 0; ni < 8; ni++)
            hmma16_z(hh[0][ni], aL0.x, aH0.x, aL0.y, aH0.y, bf[ni].x, bf[ni].y);
        #pragma unroll
        for (int ni = 0; ni < 8; ni++)
            hmma16_z(hh[1][ni], aL1.x, aH1.x, aL1.y, aH1.y, bf[ni].x, bf[ni].y);
        #pragma unroll
        for (int ni = 0; ni < 8; ni++)
            hmma16(hh[0][ni], aL0.z, aH0.z, aL0.w, aH0.w, bf[ni].z, bf[ni].w);
        #pragma unroll
        for (int ni = 0; ni < 8; ni++)
            hmma16(hh[1][ni], aL1.z, aH1.z, aL1.w, aH1.w, bf[ni].z, bf[ni].w);

        // promote 32-term fp16 chunks into fp32 accumulators
        #pragma unroll
        for (int mi = 0; mi < 2; mi++)
            #pragma unroll
            for (int ni = 0; ni < 8; ni++) {
                float2 f0 = __half22float2(*(__half2*)&hh[mi][ni][0]);
                float2 f1 = __half22float2(*(__half2*)&hh[mi][ni][1]);
                acc[mi][ni][0] += f0.x;
                acc[mi][ni][1] += f0.y;
                acc[mi][ni][2] += f1.x;
                acc[mi][ni][3] += f1.y;
            }
    }

    // store C to the split's buffer
    float* Zo = (kz == 0) ? g_Z : g_Z2;
    const int cg = tg * 2;
    #pragma unroll
    for (int mi = 0; mi < 2; mi++) {
        #pragma unroll
        for (int ni = 0; ni < 8; ni++) {
            int row = mb * 128 + wm * 32 + mi * 16 + g;
            int col = nb * 128 + wn * 64 + ni * 8 + cg;
            Zo[(size_t)row * HID + col]           = acc[mi][ni][0];
            Zo[(size_t)row * HID + col + 1]       = acc[mi][ni][1];
            Zo[(size_t)(row + 8) * HID + col]     = acc[mi][ni][2];
            Zo[(size_t)(row + 8) * HID + col + 1] = acc[mi][ni][3];
        }
    }
}

// ---------------- distributed grid barrier ----------------
__device__ __forceinline__ void grid_sync2(int t) {
    __syncthreads();
    const int tid = threadIdx.x;
    if (tid == 0) {
        __threadfence();
        *(volatile int*)&g_flags[blockIdx.x * 32] = t + 1;
    }
    if (blockIdx.x == 0) {
        if (tid < NBLK_RECUR)
            while (*(volatile int*)&g_flags[tid * 32] <= t) { }
        __syncthreads();
        if (tid == 0) { __threadfence(); g_rel = t + 1; }
    }
    if (tid == 0) { while (g_rel <= t) { } }
    __syncthreads();
}

// ---------------- Phase 2: persistent recurrence ----------------
__global__ void __launch_bounds__(256) rnn_recur(const float* __restrict__ b_h) {
    __shared__ float w_s[8][1028];
    __shared__ float sh[BSZ][132];

    const int tid = threadIdx.x;
    const int r   = tid >> 3;
    const int c   = tid & 7;
    const int col = blockIdx.x * 8 + c;

    #pragma unroll
    for (int j = tid; j < 2048; j += 256) {
        int cc = j >> 8, kq = (j & 255) * 4;
        *(float4*)&w_s[cc][kq] =
            *(const float4*)&g_WhhT[(size_t)(blockIdx.x * 8 + cc) * HID + kq];
    }
    const float bias = b_h[col];
    const uint32_t sh_r = s2u(&sh[0][0]) + r * 528;
    const uint32_t ws_c = s2u(&w_s[0][0]) + c * 4112;
    __syncthreads();

    for (int t = 0; t < T_STEPS; t++) {
        const float* hin  = g_h[t & 1];
        float*       hout = g_h[(t + 1) & 1];
        const float* Z1t  = g_Z  + (size_t)t * BSZ * HID;
        const float* Z2t  = g_Z2 + (size_t)t * BSZ * HID;

        unsigned long long a0 = 0ull, a1 = 0ull;
        for (int kc = 0; kc < HID; kc += 128) {
            __syncthreads();
            #pragma unroll
            for (int j = tid; j < 800; j += 256) {
                int rr = j >> 5, kq = (j & 31) * 4;
                *(float4*)&sh[rr][kq] = *(const float4*)&hin[rr * HID + kc + kq];
            }
            __syncthreads();
            if (r < BSZ) {
                #pragma unroll
                for (int i = 0; i < 32; i++) {
                    unsigned long long h01, h23, v01, v23;
                    asm("ld.shared.v2.u64 {%0,%1}, [%2];" : "=l"(h01), "=l"(h23) : "r"(sh_r + i * 16));
                    asm("ld.shared.v2.u64 {%0,%1}, [%2];" : "=l"(v01), "=l"(v23) : "r"(ws_c + (kc + i * 4) * 4));
                    asm("fma.rn.f32x2 %0, %1, %2, %0;" : "+l"(a0) : "l"(h01), "l"(v01));
                    asm("fma.rn.f32x2 %0, %1, %2, %0;" : "+l"(a1) : "l"(h23), "l"(v23));
                }
            }
        }
        if (r < BSZ) {
            float x0, x1, y0, y1;
            asm("mov.b64 {%0,%1}, %2;" : "=f"(x0), "=f"(x1) : "l"(a0));
            asm("mov.b64 {%0,%1}, %2;" : "=f"(y0), "=f"(y1) : "l"(a1));
            float v = (x0 + x1) + (y0 + y1);
            int idx = r * HID + col;
            hout[idx] = tanhf(Z1t[idx] + Z2t[idx] + v + bias);
        }
        grid_sync2(t);
    }
}

// ---------------- Phase 3: pool + FC + softmax ----------------
__global__ void final_k(const float* __restrict__ fc_w,
                        const float* __restrict__ fc_b,
                        float* __restrict__ out) {
    __shared__ float s0[256], s1[256];
    const float* h = g_h[0];
    int tid = threadIdx.x;
    float l0 = 0.0f, l1 = 0.0f;
    for (int j = tid; j < HID; j += 256) {
        float p = 0.0f;
        #pragma unroll
        for (int rr = 0; rr < BSZ; rr++) p += h[rr * HID + j];
        p *= (1.0f / (float)BSZ);
        l0 += p * fc_w[j * NCLS + 0];
        l1 += p * fc_w[j * NCLS + 1];
    }
    s0[tid] = l0; s1[tid] = l1;
    __syncthreads();
    for (int s = 128; s; s >>= 1) {
        if (tid < s) { s0[tid] += s0[tid + s]; s1[tid] += s1[tid + s]; }
        __syncthreads();
    }
    if (tid == 0) {
        float a = s0[0] + fc_b[0];
        float b = s1[0] + fc_b[1];
        float m = fmaxf(a, b);
        float e0 = expf(a - m), e1 = expf(b - m);
        float inv = 1.0f / (e0 + e1);
        out[0] = e0 * inv;
        out[1] = e1 * inv;
    }
}

// ---------------- launch ----------------
extern "C" void kernel_launch(void* const* d_in, const int* in_sizes, int n_in,
                              void* d_out, int out_size) {
    const float* X   = (const float*)d_in[0];
    const float* Wxh = (const float*)d_in[1];
    const float* Whh = (const float*)d_in[2];
    const float* bh  = (const float*)d_in[3];
    const float* fcw = (const float*)d_in[4];
    const float* fcb = (const float*)d_in[5];
    float* out = (float*)d_out;

    init_k<<<100, 256>>>();                          // launch 1
    transpose_k<<<dim3(32, 32), dim3(32, 8)>>>(Whh); // launch 2
    pack_all<<<dim3(KT, 58), 256>>>(X, Wxh);         // launch 3
    gemm_fp16<<<dim3(8, 50, KSPLIT), 256>>>();       // launch 4  <- ncu capture slot
    rnn_recur<<<NBLK_RECUR, 256>>>(bh);              // launch 5
    final_k<<<1, 256>>>(fcw, fcb, out);              // launch 6
}

// round 15
// speedup vs baseline: 2.2115x; 2.2115x over previous
#include <cuda_runtime.h>
#include <cuda_fp16.h>
#include <cstdint>

#define T_STEPS 256
#define BSZ     25
#define VOCAB   32000
#define HID     1024
#define NCLS    2
#define MROWS   6400
#define NBLK_R  64             // recurrence CTAs
#define KT      1000           // gemm k-tiles of 32
#define KSPLIT  2
#define KT_HALF 500
#define TILEB   8192

// ---------------- device scratch ----------------
__device__ float g_Z[MROWS * HID];
__device__ float g_Z2[MROWS * HID];
__device__ float g_hfin[BSZ * HID];
__device__ __align__(16) uint8_t g_hA[2][65536];        // fp16 h, A-fragment packed, ping-pong
__device__ __align__(16) uint8_t g_Wpk[NBLK_R * 32768]; // fp16 W_hh, B-fragment packed per CTA slice
__device__ __align__(256) uint8_t g_Apk[(size_t)50 * KT * TILEB];
__device__ __align__(256) uint8_t g_Bpk[(size_t)8  * KT * TILEB];
__device__ int   g_flags[NBLK_R * 32];
__device__ volatile int g_rel;

// ---------------- helpers ----------------
__device__ __forceinline__ uint32_t s2u(const void* p) {
    uint32_t a;
    asm("{ .reg .u64 t; cvta.to.shared.u64 t, %1; cvt.u32.u64 %0, t; }" : "=r"(a) : "l"(p));
    return a;
}
__device__ __forceinline__ void mbar_init(uint32_t m, uint32_t c) {
    asm volatile("mbarrier.init.shared.b64 [%0], %1;" :: "r"(m), "r"(c) : "memory");
}
__device__ __forceinline__ void mbar_expect(uint32_t m, uint32_t bytes) {
    asm volatile("mbarrier.arrive.expect_tx.shared.b64 _, [%0], %1;" :: "r"(m), "r"(bytes) : "memory");
}
__device__ __forceinline__ void mbar_wait(uint32_t m, uint32_t ph) {
    asm volatile(
        "{\n\t.reg .pred P;\n\t"
        "W%=:\n\t"
        "mbarrier.try_wait.parity.acquire.cta.shared::cta.b64 P, [%0], %1, 0x989680;\n\t"
        "@P bra.uni D%=;\n\t"
        "bra.uni W%=;\n\t"
        "D%=:\n\t}" :: "r"(m), "r"(ph) : "memory");
}
__device__ __forceinline__ void bulk_g2s(uint32_t dst, const void* src, uint32_t bytes, uint32_t mbar) {
    asm volatile(
        "cp.async.bulk.shared::cluster.global.mbarrier::complete_tx::bytes [%0], [%1], %2, [%3];"
        :: "r"(dst), "l"(src), "r"(bytes), "r"(mbar) : "memory");
}
// fp32-accumulate HMMA (the fast one on this chip)
__device__ __forceinline__ void hmma(float* c, uint32_t a0, uint32_t a1, uint32_t a2,
                                     uint32_t a3, uint32_t b0, uint32_t b1) {
    asm volatile(
        "mma.sync.aligned.m16n8k16.row.col.f32.f16.f16.f32 "
        "{%0,%1,%2,%3}, {%4,%5,%6,%7}, {%8,%9}, {%0,%1,%2,%3};\n"
        : "+f"(c[0]), "+f"(c[1]), "+f"(c[2]), "+f"(c[3])
        : "r"(a0), "r"(a1), "r"(a2), "r"(a3), "r"(b0), "r"(b1));
}
__device__ __forceinline__ uint4 ldg_cg128(const void* p) {
    uint4 r;
    asm volatile("ld.global.cg.v4.u32 {%0,%1,%2,%3}, [%4];"
        : "=r"(r.x), "=r"(r.y), "=r"(r.z), "=r"(r.w) : "l"(p));
    return r;
}
__device__ __forceinline__ uint32_t koff_pair(int p) {
    return (uint32_t)((p & 3) * 16 + (p >> 2) * 4);
}

// ---------------- init: zero fp16 h buffers (both, incl. pad rows), barrier state ----------------
__global__ void init_k() {
    int tid = blockIdx.x * 256 + threadIdx.x;
    if (tid == 0) g_rel = 0;
    if (tid < NBLK_R * 32) g_flags[tid] = 0;
    if (tid < 8192) ((uint4*)g_hA)[tid] = make_uint4(0, 0, 0, 0);   // 128 KB
}

// ---------------- packW: W_hh -> fp16 B-fragment layout per 16-col CTA slice ----------------
// slice cta: cols [cta*16, cta*16+16). Block layout: [kc 0..63][nt 0..1][lane][8B].
__global__ void __launch_bounds__(256) packW(const float* __restrict__ W) {
    const int cta = blockIdx.x;
    uint8_t* dst = g_Wpk + (size_t)cta * 32768;
    #pragma unroll
    for (int i = 0; i < 64; i++) {
        int e = threadIdx.x + i * 256;        // 16384 elems per slice
        int k = e >> 4, no = e & 15;
        __half hv = __float2half(W[(size_t)k * HID + cta * 16 + no]);
        int kk = k & 15, kc = k >> 4;
        int nt = no >> 3, gg = no & 7, tg = (kk & 7) >> 1;
        int off = kc * 512 + nt * 256 + (gg * 4 + tg) * 8 + ((kk >> 3) << 2) + ((kk & 1) << 1);
        *(__half*)(dst + off) = hv;
    }
}

// ---------------- pack_all: A (y<50) and B (y>=50) fp16 fragment-ordered tiles for the big GEMM ----
__global__ void __launch_bounds__(256) pack_all(const float* __restrict__ X,
                                                const float* __restrict__ Wxh) {
    const int kt = blockIdx.x;
    const int y  = blockIdx.y;
    if (y < 50) {
        uint8_t* dst = g_Apk + ((size_t)y * KT + kt) * TILEB;
        const float* src = X + (size_t)(y * 128) * VOCAB + kt * 32;
        #pragma unroll
        for (int i = 0; i < 8; i++) {
            int idx = threadIdx.x + i * 256;
            int m = idx >> 4, p = idx & 15;
            float2 v = *(const float2*)&src[(size_t)m * VOCAB + p * 2];
            __half2 h = __floats2half2_rn(v.x, v.y);
            *(uint32_t*)(dst + m * 64 + koff_pair(p)) = *(uint32_t*)&h;
        }
    } else {
        __shared__ float s[32][132];
        const int nb = y - 50;
        uint8_t* dst = g_Bpk + ((size_t)nb * KT + kt) * TILEB;
        #pragma unroll
        for (int i = 0; i < 16; i++) {
            int idx = threadIdx.x + i * 256;
            int kk = idx >> 7, n = idx & 127;
            s[kk][n] = Wxh[(size_t)(kt * 32 + kk) * HID + nb * 128 + n];
        }
        __syncthreads();
        #pragma unroll
        for (int i = 0; i < 8; i++) {
            int idx = threadIdx.x + i * 256;
            int n = idx >> 4, p = idx & 15;
            __half2 h = __floats2half2_rn(s[2 * p][n], s[2 * p + 1][n]);
            *(uint32_t*)(dst + n * 64 + koff_pair(p)) = *(uint32_t*)&h;
        }
    }
}

// ---------------- Phase 1: Z = X @ W_xh  (fp32-acc mma.sync, split-K=2; R13 best) ----------------
__global__ void __launch_bounds__(256, 2) gemm_fp16() {
    __shared__ __align__(128) uint8_t sA[2][TILEB];
    __shared__ __align__(128) uint8_t sB[2][TILEB];
    __shared__ __align__(8) uint64_t s_full[2];

    const int tid  = threadIdx.x;
    const int lane = tid & 31;
    const int warp = tid >> 5;
    const int wm   = warp & 3;
    const int wn   = warp >> 2;
    const int g    = lane >> 2;
    const int tg   = lane & 3;
    const int nb   = blockIdx.x, mb = blockIdx.y, kz = blockIdx.z;
    const int kt0  = kz * KT_HALF;

    const uint32_t mb_full[2] = { s2u(&s_full[0]), s2u(&s_full[1]) };
    if (tid == 0) { mbar_init(mb_full[0], 1); mbar_init(mb_full[1], 1); }
    __syncthreads();

    const uint8_t* Ab = g_Apk + (size_t)mb * KT * TILEB;
    const uint8_t* Bb = g_Bpk + (size_t)nb * KT * TILEB;
    const uint32_t sa0 = s2u(&sA[0][0]), sb0 = s2u(&sB[0][0]);

    if (tid == 0) {
        #pragma unroll
        for (int s = 0; s < 2; s++) {
            mbar_expect(mb_full[s], 2 * TILEB);
            bulk_g2s(sa0 + s * TILEB, Ab + (size_t)(kt0 + s) * TILEB, TILEB, mb_full[s]);
            bulk_g2s(sb0 + s * TILEB, Bb + (size_t)(kt0 + s) * TILEB, TILEB, mb_full[s]);
        }
    }

    float acc[2][8][4];
    #pragma unroll
    for (int mi = 0; mi < 2; mi++)
        #pragma unroll
        for (int ni = 0; ni < 8; ni++)
            #pragma unroll
            for (int j = 0; j < 4; j++) acc[mi][ni][j] = 0.0f;

    const uint32_t a_off = (uint32_t)((wm * 32 + g) * 64 + tg * 16);
    const uint32_t b_off = (uint32_t)((wn * 64 + g) * 64 + tg * 16);

    #pragma unroll 1
    for (int it = 0; it < KT_HALF; it++) {
        const int s  = it & 1;
        const int ph = (it >> 1) & 1;
        mbar_wait(mb_full[s], ph);

        const uint8_t* As = sA[s];
        const uint8_t* Bs = sB[s];

        uint4 aL0 = *(const uint4*)(As + a_off);
        uint4 aH0 = *(const uint4*)(As + a_off + 512);
        uint4 aL1 = *(const uint4*)(As + a_off + 1024);
        uint4 aH1 = *(const uint4*)(As + a_off + 1536);
        uint4 bf[8];
        #pragma unroll
        for (int ni = 0; ni < 8; ni++)
            bf[ni] = *(const uint4*)(Bs + b_off + ni * 512);

        __syncthreads();
        const int nk = it + 2;
        if (tid == 0 && nk < KT_HALF) {
            mbar_expect(mb_full[s], 2 * TILEB);
            bulk_g2s(sa0 + s * TILEB, Ab + (size_t)(kt0 + nk) * TILEB, TILEB, mb_full[s]);
            bulk_g2s(sb0 + s * TILEB, Bb + (size_t)(kt0 + nk) * TILEB, TILEB, mb_full[s]);
        }

        #pragma unroll
        for (int ni = 0; ni < 8; ni++)
            hmma(acc[0][ni], aL0.x, aH0.x, aL0.y, aH0.y, bf[ni].x, bf[ni].y);
        #pragma unroll
        for (int ni = 0; ni < 8; ni++)
            hmma(acc[1][ni], aL1.x, aH1.x, aL1.y, aH1.y, bf[ni].x, bf[ni].y);
        #pragma unroll
        for (int ni = 0; ni < 8; ni++)
            hmma(acc[0][ni], aL0.z, aH0.z, aL0.w, aH0.w, bf[ni].z, bf[ni].w);
        #pragma unroll
        for (int ni = 0; ni < 8; ni++)
            hmma(acc[1][ni], aL1.z, aH1.z, aL1.w, aH1.w, bf[ni].z, bf[ni].w);
    }

    float* Zo = (kz == 0) ? g_Z : g_Z2;
    const int cg = tg * 2;
    #pragma unroll
    for (int mi = 0; mi < 2; mi++) {
        #pragma unroll
        for (int ni = 0; ni < 8; ni++) {
            int row = mb * 128 + wm * 32 + mi * 16 + g;
            int col = nb * 128 + wn * 64 + ni * 8 + cg;
            Zo[(size_t)row * HID + col]           = acc[mi][ni][0];
            Zo[(size_t)row * HID + col + 1]       = acc[mi][ni][1];
            Zo[(size_t)(row + 8) * HID + col]     = acc[mi][ni][2];
            Zo[(size_t)(row + 8) * HID + col + 1] = acc[mi][ni][3];
        }
    }
}

// ---------------- distributed grid barrier (64 CTAs) ----------------
__device__ __forceinline__ void grid_sync2(int t) {
    __syncthreads();
    const int tid = threadIdx.x;
    if (tid == 0) {
        __threadfence();
        *(volatile int*)&g_flags[blockIdx.x * 32] = t + 1;
    }
    if (blockIdx.x == 0) {
        if (tid < NBLK_R)
            while (*(volatile int*)&g_flags[tid * 32] <= t) { }
        __syncthreads();
        if (tid == 0) { __threadfence(); g_rel = t + 1; }
    }
    if (tid == 0) { while (g_rel <= t) { } }
    __syncthreads();
}

// ---------------- Phase 2: tensor-core recurrence ----------------
// 64 CTAs x 256 thr; CTA owns cols [cta*16, +16). Per step: M=32(25)xN=16xK=1024 HMMA.
// Warps: mt = w&1, nt = (w>>1)&1, ks = w>>2 (k-split halves). h fp16 in A-fragment
// layout in global (ping-pong), read .cg; W fp16 B-fragments in smem (staged once).
__global__ void __launch_bounds__(256) rnn_tc(const float* __restrict__ b_h) {
    __shared__ __align__(16) uint8_t sW[32768];
    __shared__ float4 sRed[4][32];

    const int tid = threadIdx.x, lane = tid & 31, warp = tid >> 5;
    const int cta = blockIdx.x;
    const int mt = warp & 1, nt = (warp >> 1) & 1, ks = warp >> 2;
    const int g = lane >> 2, tg = lane & 3;

    // stage W slice (32KB)
    for (int i = tid; i < 2048; i += 256)
        *(uint4*)(sW + i * 16) = *(const uint4*)(g_Wpk + (size_t)cta * 32768 + i * 16);

    const int c0 = cta * 16 + nt * 8 + 2 * tg;
    const float bias0 = b_h[c0], bias1 = b_h[c0 + 1];
    const int r0 = mt * 16 + g;       // always < 25
    const int r1 = r0 + 8;
    const bool v1 = (r1 < BSZ);
    const uint32_t sW_u = s2u(sW);
    __syncthreads();

    for (int t = 0; t < T_STEPS; t++) {
        const uint8_t* hIn = g_hA[t & 1];
        uint8_t*       hOut = g_hA[(t + 1) & 1];

        // Z prefetch (epilogue warps only) — loads issued before compute, used after
        float z00 = 0.f, z01 = 0.f, z10 = 0.f, z11 = 0.f;
        if (ks == 0) {
            const float* Z1t = g_Z  + (size_t)t * BSZ * HID;
            const float* Z2t = g_Z2 + (size_t)t * BSZ * HID;
            int i0 = r0 * HID + c0;
            z00 = Z1t[i0] + Z2t[i0];
            z01 = Z1t[i0 + 1] + Z2t[i0 + 1];
            if (v1) {
                int i1 = r1 * HID + c0;
                z10 = Z1t[i1] + Z2t[i1];
                z11 = Z1t[i1 + 1] + Z2t[i1 + 1];
            }
        }

        // HMMA over this warp's 32 k-chunks (k = 512*ks .. +511)
        float acc0[4] = {0, 0, 0, 0}, acc1[4] = {0, 0, 0, 0};
        const int kc0 = ks * 32;
        const uint8_t* aBase = hIn + mt * 512 + lane * 16;
        uint4 ab[2][8];
        #pragma unroll
        for (int j = 0; j < 8; j++)
            ab[0][j] = ldg_cg128(aBase + (size_t)(kc0 + j) * 1024);
        #pragma unroll
        for (int v = 0; v < 4; v++) {
            const int cur = v & 1;
            if (v < 3) {
                #pragma unroll
                for (int j = 0; j < 8; j++)
                    ab[cur ^ 1][j] = ldg_cg128(aBase + (size_t)(kc0 + (v + 1) * 8 + j) * 1024);
            }
            #pragma unroll
            for (int j = 0; j < 8; j++) {
                const int kc = kc0 + v * 8 + j;
                uint32_t b0, b1;
                asm("ld.shared.v2.u32 {%0,%1}, [%2];" : "=r"(b0), "=r"(b1)
                    : "r"(sW_u + kc * 512 + nt * 256 + lane * 8));
                hmma((j & 1) ? acc1 : acc0,
                     ab[cur][j].x, ab[cur][j].y, ab[cur][j].z, ab[cur][j].w, b0, b1);
            }
        }
        float accf[4];
        #pragma unroll
        for (int q = 0; q < 4; q++) accf[q] = acc0[q] + acc1[q];

        // k-split reduce
        if (ks == 1)
            sRed[warp - 4][lane] = make_float4(accf[0], accf[1], accf[2], accf[3]);
        __syncthreads();

        if (ks == 0) {
            float4 o = sRed[warp][lane];
            accf[0] += o.x; accf[1] += o.y; accf[2] += o.z; accf[3] += o.w;

            float h00 = tanhf(z00 + accf[0] + bias0);
            float h01 = tanhf(z01 + accf[1] + bias1);
            __half2 p0 = __floats2half2_rn(h00, h01);
            // packed write: this CTA's cols live in k-chunk kc == cta
            uint32_t* dst = (uint32_t*)(hOut + cta * 1024 + mt * 512 + (g * 4 + tg) * 16 + nt * 8);
            dst[0] = *(uint32_t*)&p0;
            if (v1) {
                float h10 = tanhf(z10 + accf[2] + bias0);
                float h11 = tanhf(z11 + accf[3] + bias1);
                __half2 p1 = __floats2half2_rn(h10, h11);
                dst[1] = *(uint32_t*)&p1;
                if (t == T_STEPS - 1) {
                    g_hfin[r1 * HID + c0]     = h10;
                    g_hfin[r1 * HID + c0 + 1] = h11;
                }
            }
            if (t == T_STEPS - 1) {
                g_hfin[r0 * HID + c0]     = h00;
                g_hfin[r0 * HID + c0 + 1] = h01;
            }
        }

        grid_sync2(t);
    }
}

// ---------------- Phase 3: pool + FC + softmax ----------------
__global__ void final_k(const float* __restrict__ fc_w,
                        const float* __restrict__ fc_b,
                        float* __restrict__ out) {
    __shared__ float s0[256], s1[256];
    int tid = threadIdx.x;
    float l0 = 0.0f, l1 = 0.0f;
    for (int j = tid; j < HID; j += 256) {
        float p = 0.0f;
        #pragma unroll
        for (int rr = 0; rr < BSZ; rr++) p += g_hfin[rr * HID + j];
        p *= (1.0f / (float)BSZ);
        l0 += p * fc_w[j * NCLS + 0];
        l1 += p * fc_w[j * NCLS + 1];
    }
    s0[tid] = l0; s1[tid] = l1;
    __syncthreads();
    for (int s = 128; s; s >>= 1) {
        if (tid < s) { s0[tid] += s0[tid + s]; s1[tid] += s1[tid + s]; }
        __syncthreads();
    }
    if (tid == 0) {
        float a = s0[0] + fc_b[0];
        float b = s1[0] + fc_b[1];
        float m = fmaxf(a, b);
        float e0 = expf(a - m), e1 = expf(b - m);
        float inv = 1.0f / (e0 + e1);
        out[0] = e0 * inv;
        out[1] = e1 * inv;
    }
}

// ---------------- launch ----------------
extern "C" void kernel_launch(void* const* d_in, const int* in_sizes, int n_in,
                              void* d_out, int out_size) {
    const float* X   = (const float*)d_in[0];
    const float* Wxh = (const float*)d_in[1];
    const float* Whh = (const float*)d_in[2];
    const float* bh  = (const float*)d_in[3];
    const float* fcw = (const float*)d_in[4];
    const float* fcb = (const float*)d_in[5];
    float* out = (float*)d_out;

    init_k<<<100, 256>>>();                          // 1
    packW<<<NBLK_R, 256>>>(Whh);                     // 2
    pack_all<<<dim3(KT, 58), 256>>>(X, Wxh);         // 3
    gemm_fp16<<<dim3(8, 50, KSPLIT), 256>>>();       // 4
    rnn_tc<<<NBLK_R, 256>>>(bh);                     // 5
    final_k<<<1, 256>>>(fcw, fcb, out);              // 6
}

// round 16
// speedup vs baseline: 2.4300x; 1.0988x over previous
#include <cuda_runtime.h>
#include <cuda_fp16.h>
#include <cstdint>

#define T_STEPS 256
#define BSZ     25
#define VOCAB   32000
#define HID     1024
#define NCLS    2
#define MROWS   6400
#define NBLK_R  64             // recurrence CTAs
#define NBLK_G  128            // gemm worker CTAs
#define NTILES  800            // 50 mb x 8 nb x 2 kz
#define KT      1000           // k-tiles of 32
#define KT_HALF 500
#define TILEB   8192

// ---------------- device scratch ----------------
__device__ float g_Z[MROWS * HID];
__device__ float g_Z2[MROWS * HID];
__device__ float g_hfin[BSZ * HID];
__device__ __align__(16) uint8_t g_hA[2][65536];        // fp16 h, A-fragment packed, ping-pong
__device__ __align__(16) uint8_t g_Wpk[NBLK_R * 32768]; // fp16 W_hh, B-fragment packed
__device__ __align__(256) uint8_t g_Apk[(size_t)50 * KT * TILEB];
__device__ __align__(256) uint8_t g_Bpk[(size_t)8  * KT * TILEB];
__device__ int g_flags[NBLK_R * 32];
__device__ int g_tile;
__device__ int g_mbcnt[50];

// ---------------- helpers ----------------
__device__ __forceinline__ uint32_t s2u(const void* p) {
    uint32_t a;
    asm("{ .reg .u64 t; cvta.to.shared.u64 t, %1; cvt.u32.u64 %0, t; }" : "=r"(a) : "l"(p));
    return a;
}
__device__ __forceinline__ void mbar_init(uint32_t m, uint32_t c) {
    asm volatile("mbarrier.init.shared.b64 [%0], %1;" :: "r"(m), "r"(c) : "memory");
}
__device__ __forceinline__ void mbar_expect(uint32_t m, uint32_t bytes) {
    asm volatile("mbarrier.arrive.expect_tx.shared.b64 _, [%0], %1;" :: "r"(m), "r"(bytes) : "memory");
}
__device__ __forceinline__ void mbar_wait(uint32_t m, uint32_t ph) {
    asm volatile(
        "{\n\t.reg .pred P;\n\t"
        "W%=:\n\t"
        "mbarrier.try_wait.parity.acquire.cta.shared::cta.b64 P, [%0], %1, 0x989680;\n\t"
        "@P bra.uni D%=;\n\t"
        "bra.uni W%=;\n\t"
        "D%=:\n\t}" :: "r"(m), "r"(ph) : "memory");
}
__device__ __forceinline__ void bulk_g2s(uint32_t dst, const void* src, uint32_t bytes, uint32_t mbar) {
    asm volatile(
        "cp.async.bulk.shared::cluster.global.mbarrier::complete_tx::bytes [%0], [%1], %2, [%3];"
        :: "r"(dst), "l"(src), "r"(bytes), "r"(mbar) : "memory");
}
__device__ __forceinline__ void hmma(float* c, uint32_t a0, uint32_t a1, uint32_t a2,
                                     uint32_t a3, uint32_t b0, uint32_t b1) {
    asm volatile(
        "mma.sync.aligned.m16n8k16.row.col.f32.f16.f16.f32 "
        "{%0,%1,%2,%3}, {%4,%5,%6,%7}, {%8,%9}, {%0,%1,%2,%3};\n"
        : "+f"(c[0]), "+f"(c[1]), "+f"(c[2]), "+f"(c[3])
        : "r"(a0), "r"(a1), "r"(a2), "r"(a3), "r"(b0), "r"(b1));
}
__device__ __forceinline__ uint4 ldg_cg128(const void* p) {
    uint4 r;
    asm volatile("ld.global.cg.v4.u32 {%0,%1,%2,%3}, [%4];"
        : "=r"(r.x), "=r"(r.y), "=r"(r.z), "=r"(r.w) : "l"(p));
    return r;
}
__device__ __forceinline__ float2 ldg_cg64f(const float* p) {
    float2 r;
    asm volatile("ld.global.cg.v2.f32 {%0,%1}, [%2];" : "=f"(r.x), "=f"(r.y) : "l"(p));
    return r;
}
__device__ __forceinline__ uint32_t koff_pair(int p) {
    return (uint32_t)((p & 3) * 16 + (p >> 2) * 4);
}

// ---------------- init: zero h buffers + all control state (runs every replay) ----------------
__global__ void init_k() {
    int tid = blockIdx.x * 256 + threadIdx.x;
    if (tid == 0) g_tile = 0;
    if (tid < 50) g_mbcnt[tid] = 0;
    if (tid < NBLK_R * 32) g_flags[tid] = 0;
    if (tid < 8192) ((uint4*)g_hA)[tid] = make_uint4(0, 0, 0, 0);   // 128 KB
}

// ---------------- packW: W_hh -> fp16 B-fragment layout per 16-col slice ----------------
__global__ void __launch_bounds__(256) packW(const float* __restrict__ W) {
    const int cta = blockIdx.x;
    uint8_t* dst = g_Wpk + (size_t)cta * 32768;
    #pragma unroll
    for (int i = 0; i < 64; i++) {
        int e = threadIdx.x + i * 256;
        int k = e >> 4, no = e & 15;
        __half hv = __float2half(W[(size_t)k * HID + cta * 16 + no]);
        int kk = k & 15, kc = k >> 4;
        int nt = no >> 3, gg = no & 7, tg = (kk & 7) >> 1;
        int off = kc * 512 + nt * 256 + (gg * 4 + tg) * 8 + ((kk >> 3) << 2) + ((kk & 1) << 1);
        *(__half*)(dst + off) = hv;
    }
}

// ---------------- pack_all: A (y<50) and B (y>=50) fp16 fragment-ordered tiles ----------------
__global__ void __launch_bounds__(256) pack_all(const float* __restrict__ X,
                                                const float* __restrict__ Wxh) {
    const int kt = blockIdx.x;
    const int y  = blockIdx.y;
    if (y < 50) {
        uint8_t* dst = g_Apk + ((size_t)y * KT + kt) * TILEB;
        const float* src = X + (size_t)(y * 128) * VOCAB + kt * 32;
        #pragma unroll
        for (int i = 0; i < 8; i++) {
            int idx = threadIdx.x + i * 256;
            int m = idx >> 4, p = idx & 15;
            float2 v = *(const float2*)&src[(size_t)m * VOCAB + p * 2];
            __half2 h = __floats2half2_rn(v.x, v.y);
            *(uint32_t*)(dst + m * 64 + koff_pair(p)) = *(uint32_t*)&h;
        }
    } else {
        __shared__ float s[32][132];
        const int nb = y - 50;
        uint8_t* dst = g_Bpk + ((size_t)nb * KT + kt) * TILEB;
        #pragma unroll
        for (int i = 0; i < 16; i++) {
            int idx = threadIdx.x + i * 256;
            int kk = idx >> 7, n = idx & 127;
            s[kk][n] = Wxh[(size_t)(kt * 32 + kk) * HID + nb * 128 + n];
        }
        __syncthreads();
        #pragma unroll
        for (int i = 0; i < 8; i++) {
            int idx = threadIdx.x + i * 256;
            int n = idx >> 4, p = idx & 15;
            __half2 h = __floats2half2_rn(s[2 * p][n], s[2 * p + 1][n]);
            *(uint32_t*)(dst + n * 64 + koff_pair(p)) = *(uint32_t*)&h;
        }
    }
}

// ---------------- all-to-all grid barrier among 64 recurrence CTAs ----------------
__device__ __forceinline__ void grid_sync_aa(int t) {
    __syncthreads();
    if (threadIdx.x == 0) {
        __threadfence();
        *(volatile int*)&g_flags[blockIdx.x * 32] = t + 1;
    }
    if (threadIdx.x < NBLK_R)
        while (*(volatile int*)&g_flags[threadIdx.x * 32] <= t) { }
    __syncthreads();
}

// ---------------- fused kernel: 64 recurrence CTAs + 128 gemm workers ----------------
// All 192 CTAs co-resident (<=128 regs, 34.8KB smem -> capacity 296). Gemm workers
// steal (mb,nb,kz) tiles mb-ascending and publish per-mb completion; recurrence
// gates each step on mbcnt of the last row it needs, so it trails the gemm.
__global__ void __launch_bounds__(256, 2) fused_k(const float* __restrict__ b_h) {
    __shared__ __align__(128) uint8_t sh[34816];
    __shared__ __align__(8) uint64_t s_full[2];
    __shared__ int s_tile;

    const int tid = threadIdx.x, lane = tid & 31, warp = tid >> 5;

    if (blockIdx.x >= NBLK_R) {
        // ================= GEMM worker =================
        const uint32_t mb_full[2] = { s2u(&s_full[0]), s2u(&s_full[1]) };
        if (tid == 0) { mbar_init(mb_full[0], 1); mbar_init(mb_full[1], 1); }
        const int wm = warp & 3, wn = warp >> 2, g = lane >> 2, tg = lane & 3;
        const uint32_t sa0 = s2u(sh);
        const uint32_t sb0 = s2u(sh + 2 * TILEB);
        const uint32_t a_off = (uint32_t)((wm * 32 + g) * 64 + tg * 16);
        const uint32_t b_off = (uint32_t)((wn * 64 + g) * 64 + tg * 16);
        __syncthreads();

        for (;;) {
            if (tid == 0) s_tile = atomicAdd(&g_tile, 1);
            __syncthreads();
            const int tile = s_tile;
            if (tile >= NTILES) break;
            const int mb = tile >> 4, sub = tile & 15, nb = sub & 7, kz = sub >> 3;
            const int kt0 = kz * KT_HALF;
            const uint8_t* Ab = g_Apk + (size_t)mb * KT * TILEB;
            const uint8_t* Bb = g_Bpk + (size_t)nb * KT * TILEB;

            if (tid == 0) {
                #pragma unroll
                for (int s = 0; s < 2; s++) {
                    mbar_expect(mb_full[s], 2 * TILEB);
                    bulk_g2s(sa0 + s * TILEB, Ab + (size_t)(kt0 + s) * TILEB, TILEB, mb_full[s]);
                    bulk_g2s(sb0 + s * TILEB, Bb + (size_t)(kt0 + s) * TILEB, TILEB, mb_full[s]);
                }
            }

            float acc[2][8][4];
            #pragma unroll
            for (int mi = 0; mi < 2; mi++)
                #pragma unroll
                for (int ni = 0; ni < 8; ni++)
                    #pragma unroll
                    for (int j = 0; j < 4; j++) acc[mi][ni][j] = 0.0f;

            #pragma unroll 1
            for (int it = 0; it < KT_HALF; it++) {
                const int s  = it & 1;
                const int ph = (it >> 1) & 1;
                mbar_wait(mb_full[s], ph);

                const uint8_t* As = sh + s * TILEB;
                const uint8_t* Bs = sh + 2 * TILEB + s * TILEB;

                uint4 aL0 = *(const uint4*)(As + a_off);
                uint4 aH0 = *(const uint4*)(As + a_off + 512);
                uint4 aL1 = *(const uint4*)(As + a_off + 1024);
                uint4 aH1 = *(const uint4*)(As + a_off + 1536);
                uint4 bf[8];
                #pragma unroll
                for (int ni = 0; ni < 8; ni++)
                    bf[ni] = *(const uint4*)(Bs + b_off + ni * 512);

                __syncthreads();
                const int nk = it + 2;
                if (tid == 0 && nk < KT_HALF) {
                    mbar_expect(mb_full[s], 2 * TILEB);
                    bulk_g2s(sa0 + s * TILEB, Ab + (size_t)(kt0 + nk) * TILEB, TILEB, mb_full[s]);
                    bulk_g2s(sb0 + s * TILEB, Bb + (size_t)(kt0 + nk) * TILEB, TILEB, mb_full[s]);
                }

                #pragma unroll
                for (int ni = 0; ni < 8; ni++)
                    hmma(acc[0][ni], aL0.x, aH0.x, aL0.y, aH0.y, bf[ni].x, bf[ni].y);
                #pragma unroll
                for (int ni = 0; ni < 8; ni++)
                    hmma(acc[1][ni], aL1.x, aH1.x, aL1.y, aH1.y, bf[ni].x, bf[ni].y);
                #pragma unroll
                for (int ni = 0; ni < 8; ni++)
                    hmma(acc[0][ni], aL0.z, aH0.z, aL0.w, aH0.w, bf[ni].z, bf[ni].w);
                #pragma unroll
                for (int ni = 0; ni < 8; ni++)
                    hmma(acc[1][ni], aL1.z, aH1.z, aL1.w, aH1.w, bf[ni].z, bf[ni].w);
            }

            float* Zo = (kz == 0) ? g_Z : g_Z2;
            const int cg = tg * 2;
            #pragma unroll
            for (int mi = 0; mi < 2; mi++) {
                #pragma unroll
                for (int ni = 0; ni < 8; ni++) {
                    int row = mb * 128 + wm * 32 + mi * 16 + g;
                    int col = nb * 128 + wn * 64 + ni * 8 + cg;
                    Zo[(size_t)row * HID + col]           = acc[mi][ni][0];
                    Zo[(size_t)row * HID + col + 1]       = acc[mi][ni][1];
                    Zo[(size_t)(row + 8) * HID + col]     = acc[mi][ni][2];
                    Zo[(size_t)(row + 8) * HID + col + 1] = acc[mi][ni][3];
                }
            }
            __threadfence();
            __syncthreads();
            if (tid == 0) atomicAdd(&g_mbcnt[mb], 1);
        }
        return;
    }

    // ================= tensor-core recurrence =================
    uint8_t* sW = sh;                                       // 32 KB
    float4 (*sRed)[32] = (float4(*)[32])(sh + 32768);       // 2 KB

    const int cta = blockIdx.x;
    const int mt = warp & 1, nt = (warp >> 1) & 1, ks = warp >> 2;
    const int g = lane >> 2, tg = lane & 3;

    for (int i = tid; i < 2048; i += 256)
        *(uint4*)(sW + i * 16) = *(const uint4*)(g_Wpk + (size_t)cta * 32768 + i * 16);

    const int c0 = cta * 16 + nt * 8 + 2 * tg;
    const float bias0 = b_h[c0], bias1 = b_h[c0 + 1];
    const int r0 = mt * 16 + g;
    const int r1 = r0 + 8;
    const bool v1 = (r1 < BSZ);
    const uint32_t sW_u = s2u(sW);
    __syncthreads();

    int mb_ready = -1;
    for (int t = 0; t < T_STEPS; t++) {
        // gate on gemm progress: last row needed is t*25+24 -> mb index >>7
        const int mbn = (t * 25 + 24) >> 7;
        if (mbn != mb_ready) {
            if (tid == 0)
                while (*(volatile int*)&g_mbcnt[mbn] < 16) { }
            __syncthreads();
            mb_ready = mbn;
        }

        const uint8_t* hIn  = g_hA[t & 1];
        uint8_t*       hOut = g_hA[(t + 1) & 1];

        float z00 = 0.f, z01 = 0.f, z10 = 0.f, z11 = 0.f;
        if (ks == 0) {
            const float* Z1t = g_Z  + (size_t)t * BSZ * HID;
            const float* Z2t = g_Z2 + (size_t)t * BSZ * HID;
            int i0 = r0 * HID + c0;
            float2 a = ldg_cg64f(Z1t + i0), b = ldg_cg64f(Z2t + i0);
            z00 = a.x + b.x; z01 = a.y + b.y;
            if (v1) {
                int i1 = r1 * HID + c0;
                float2 c = ldg_cg64f(Z1t + i1), d = ldg_cg64f(Z2t + i1);
                z10 = c.x + d.x; z11 = c.y + d.y;
            }
        }

        float acc0[4] = {0, 0, 0, 0}, acc1[4] = {0, 0, 0, 0};
        const int kc0 = ks * 32;
        const uint8_t* aBase = hIn + mt * 512 + lane * 16;
        uint4 ab[2][8];
        #pragma unroll
        for (int j = 0; j < 8; j++)
            ab[0][j] = ldg_cg128(aBase + (size_t)(kc0 + j) * 1024);
        #pragma unroll
        for (int v = 0; v < 4; v++) {
            const int cur = v & 1;
            if (v < 3) {
                #pragma unroll
                for (int j = 0; j < 8; j++)
                    ab[cur ^ 1][j] = ldg_cg128(aBase + (size_t)(kc0 + (v + 1) * 8 + j) * 1024);
            }
            #pragma unroll
            for (int j = 0; j < 8; j++) {
                const int kc = kc0 + v * 8 + j;
                uint32_t b0, b1;
                asm("ld.shared.v2.u32 {%0,%1}, [%2];" : "=r"(b0), "=r"(b1)
                    : "r"(sW_u + kc * 512 + nt * 256 + lane * 8));
                hmma((j & 1) ? acc1 : acc0,
                     ab[cur][j].x, ab[cur][j].y, ab[cur][j].z, ab[cur][j].w, b0, b1);
            }
        }
        float accf[4];
        #pragma unroll
        for (int q = 0; q < 4; q++) accf[q] = acc0[q] + acc1[q];

        if (ks == 1)
            sRed[warp - 4][lane] = make_float4(accf[0], accf[1], accf[2], accf[3]);
        __syncthreads();

        if (ks == 0) {
            float4 o = sRed[warp][lane];
            accf[0] += o.x; accf[1] += o.y; accf[2] += o.z; accf[3] += o.w;

            float h00 = tanhf(z00 + accf[0] + bias0);
            float h01 = tanhf(z01 + accf[1] + bias1);
            __half2 p0 = __floats2half2_rn(h00, h01);
            uint32_t* dst = (uint32_t*)(hOut + cta * 1024 + mt * 512 + (g * 4 + tg) * 16 + nt * 8);
            dst[0] = *(uint32_t*)&p0;
            if (v1) {
                float h10 = tanhf(z10 + accf[2] + bias0);
                float h11 = tanhf(z11 + accf[3] + bias1);
                __half2 p1 = __floats2half2_rn(h10, h11);
                dst[1] = *(uint32_t*)&p1;
                if (t == T_STEPS - 1) {
                    g_hfin[r1 * HID + c0]     = h10;
                    g_hfin[r1 * HID + c0 + 1] = h11;
                }
            }
            if (t == T_STEPS - 1) {
                g_hfin[r0 * HID + c0]     = h00;
                g_hfin[r0 * HID + c0 + 1] = h01;
            }
        }

        grid_sync_aa(t);
    }
}

// ---------------- pool + FC + softmax ----------------
__global__ void final_k(const float* __restrict__ fc_w,
                        const float* __restrict__ fc_b,
                        float* __restrict__ out) {
    __shared__ float s0[256], s1[256];
    int tid = threadIdx.x;
    float l0 = 0.0f, l1 = 0.0f;
    for (int j = tid; j < HID; j += 256) {
        float p = 0.0f;
        #pragma unroll
        for (int rr = 0; rr < BSZ; rr++) p += g_hfin[rr * HID + j];
        p *= (1.0f / (float)BSZ);
        l0 += p * fc_w[j * NCLS + 0];
        l1 += p * fc_w[j * NCLS + 1];
    }
    s0[tid] = l0; s1[tid] = l1;
    __syncthreads();
    for (int s = 128; s; s >>= 1) {
        if (tid < s) { s0[tid] += s0[tid + s]; s1[tid] += s1[tid + s]; }
        __syncthreads();
    }
    if (tid == 0) {
        float a = s0[0] + fc_b[0];
        float b = s1[0] + fc_b[1];
        float m = fmaxf(a, b);
        float e0 = expf(a - m), e1 = expf(b - m);
        float inv = 1.0f / (e0 + e1);
        out[0] = e0 * inv;
        out[1] = e1 * inv;
    }
}

// ---------------- launch ----------------
extern "C" void kernel_launch(void* const* d_in, const int* in_sizes, int n_in,
                              void* d_out, int out_size) {
    const float* X   = (const float*)d_in[0];
    const float* Wxh = (const float*)d_in[1];
    const float* Whh = (const float*)d_in[2];
    const float* bh  = (const float*)d_in[3];
    const float* fcw = (const float*)d_in[4];
    const float* fcb = (const float*)d_in[5];
    float* out = (float*)d_out;

    init_k<<<100, 256>>>();                          // 1
    packW<<<NBLK_R, 256>>>(Whh);                     // 2
    pack_all<<<dim3(KT, 58), 256>>>(X, Wxh);         // 3
    fused_k<<<NBLK_R + NBLK_G, 256>>>(bh);           // 4  <- ncu capture slot
    final_k<<<1, 256>>>(fcw, fcb, out);              // 5
}

// round 17
// speedup vs baseline: 3.1701x; 1.3046x over previous
#include <cuda_runtime.h>
#include <cuda_fp16.h>
#include <cstdint>

#define T_STEPS 256
#define BSZ     25
#define VOCAB   32000
#define HID     1024
#define NCLS    2
#define MROWS   6400
#define NBLK_R  64             // recurrence CTAs
#define NBLK_G  232            // gemm worker CTAs (64+232 = 296 = 2/SM capacity)
#define NTILES  800            // 50 mb x 8 nb x 2 kz
#define KT      1000           // k-tiles of 32
#define KT_HALF 500
#define TILEB   8192

// ---------------- device scratch ----------------
__device__ float g_Z[MROWS * HID];
__device__ float g_Z2[MROWS * HID];
__device__ float g_hfin[BSZ * HID];
__device__ __align__(16) uint8_t g_hA[2][65536];        // fp16 h, A-fragment packed, ping-pong
__device__ __align__(16) uint8_t g_Wpk[NBLK_R * 32768]; // fp16 W_hh, B-fragment packed
__device__ __align__(256) uint8_t g_Apk[(size_t)50 * KT * TILEB];
__device__ __align__(256) uint8_t g_Bpk[(size_t)8  * KT * TILEB];
__device__ int g_flags[NBLK_R * 32];
__device__ int g_tile;
__device__ int g_mbcnt[50];

// ---------------- helpers ----------------
__device__ __forceinline__ uint32_t s2u(const void* p) {
    uint32_t a;
    asm("{ .reg .u64 t; cvta.to.shared.u64 t, %1; cvt.u32.u64 %0, t; }" : "=r"(a) : "l"(p));
    return a;
}
__device__ __forceinline__ void mbar_init(uint32_t m, uint32_t c) {
    asm volatile("mbarrier.init.shared.b64 [%0], %1;" :: "r"(m), "r"(c) : "memory");
}
__device__ __forceinline__ void mbar_expect(uint32_t m, uint32_t bytes) {
    asm volatile("mbarrier.arrive.expect_tx.shared.b64 _, [%0], %1;" :: "r"(m), "r"(bytes) : "memory");
}
__device__ __forceinline__ void mbar_wait(uint32_t m, uint32_t ph) {
    asm volatile(
        "{\n\t.reg .pred P;\n\t"
        "W%=:\n\t"
        "mbarrier.try_wait.parity.acquire.cta.shared::cta.b64 P, [%0], %1, 0x989680;\n\t"
        "@P bra.uni D%=;\n\t"
        "bra.uni W%=;\n\t"
        "D%=:\n\t}" :: "r"(m), "r"(ph) : "memory");
}
__device__ __forceinline__ void bulk_g2s(uint32_t dst, const void* src, uint32_t bytes, uint32_t mbar) {
    asm volatile(
        "cp.async.bulk.shared::cluster.global.mbarrier::complete_tx::bytes [%0], [%1], %2, [%3];"
        :: "r"(dst), "l"(src), "r"(bytes), "r"(mbar) : "memory");
}
__device__ __forceinline__ void hmma(float* c, uint32_t a0, uint32_t a1, uint32_t a2,
                                     uint32_t a3, uint32_t b0, uint32_t b1) {
    asm volatile(
        "mma.sync.aligned.m16n8k16.row.col.f32.f16.f16.f32 "
        "{%0,%1,%2,%3}, {%4,%5,%6,%7}, {%8,%9}, {%0,%1,%2,%3};\n"
        : "+f"(c[0]), "+f"(c[1]), "+f"(c[2]), "+f"(c[3])
        : "r"(a0), "r"(a1), "r"(a2), "r"(a3), "r"(b0), "r"(b1));
}
__device__ __forceinline__ uint4 ldg_cg128(const void* p) {
    uint4 r;
    asm volatile("ld.global.cg.v4.u32 {%0,%1,%2,%3}, [%4];"
        : "=r"(r.x), "=r"(r.y), "=r"(r.z), "=r"(r.w) : "l"(p));
    return r;
}
__device__ __forceinline__ float2 ldg_cg64f(const float* p) {
    float2 r;
    asm volatile("ld.global.cg.v2.f32 {%0,%1}, [%2];" : "=f"(r.x), "=f"(r.y) : "l"(p));
    return r;
}
__device__ __forceinline__ uint32_t koff_pair(int p) {
    return (uint32_t)((p & 3) * 16 + (p >> 2) * 4);
}

// ---------------- init: zero h buffers + all control state (runs every replay) ----------------
__global__ void init_k() {
    int tid = blockIdx.x * 256 + threadIdx.x;
    if (tid == 0) g_tile = 0;
    if (tid < 50) g_mbcnt[tid] = 0;
    if (tid < NBLK_R * 32) g_flags[tid] = 0;
    if (tid < 8192) ((uint4*)g_hA)[tid] = make_uint4(0, 0, 0, 0);   // 128 KB
}

// ---------------- packW: W_hh -> fp16 B-fragment layout per 16-col slice ----------------
__global__ void __launch_bounds__(256) packW(const float* __restrict__ W) {
    const int cta = blockIdx.x;
    uint8_t* dst = g_Wpk + (size_t)cta * 32768;
    #pragma unroll
    for (int i = 0; i < 64; i++) {
        int e = threadIdx.x + i * 256;
        int k = e >> 4, no = e & 15;
        __half hv = __float2half(W[(size_t)k * HID + cta * 16 + no]);
        int kk = k & 15, kc = k >> 4;
        int nt = no >> 3, gg = no & 7, tg = (kk & 7) >> 1;
        int off = kc * 512 + nt * 256 + (gg * 4 + tg) * 8 + ((kk >> 3) << 2) + ((kk & 1) << 1);
        *(__half*)(dst + off) = hv;
    }
}

// ---------------- pack_all: A (y<50) and B (y>=50) fp16 fragment-ordered tiles ----------------
__global__ void __launch_bounds__(256) pack_all(const float* __restrict__ X,
                                                const float* __restrict__ Wxh) {
    const int kt = blockIdx.x;
    const int y  = blockIdx.y;
    if (y < 50) {
        uint8_t* dst = g_Apk + ((size_t)y * KT + kt) * TILEB;
        const float* src = X + (size_t)(y * 128) * VOCAB + kt * 32;
        #pragma unroll
        for (int i = 0; i < 8; i++) {
            int idx = threadIdx.x + i * 256;
            int m = idx >> 4, p = idx & 15;
            float2 v = *(const float2*)&src[(size_t)m * VOCAB + p * 2];
            __half2 h = __floats2half2_rn(v.x, v.y);
            *(uint32_t*)(dst + m * 64 + koff_pair(p)) = *(uint32_t*)&h;
        }
    } else {
        __shared__ float s[32][132];
        const int nb = y - 50;
        uint8_t* dst = g_Bpk + ((size_t)nb * KT + kt) * TILEB;
        #pragma unroll
        for (int i = 0; i < 16; i++) {
            int idx = threadIdx.x + i * 256;
            int kk = idx >> 7, n = idx & 127;
            s[kk][n] = Wxh[(size_t)(kt * 32 + kk) * HID + nb * 128 + n];
        }
        __syncthreads();
        #pragma unroll
        for (int i = 0; i < 8; i++) {
            int idx = threadIdx.x + i * 256;
            int n = idx >> 4, p = idx & 15;
            __half2 h = __floats2half2_rn(s[2 * p][n], s[2 * p + 1][n]);
            *(uint32_t*)(dst + n * 64 + koff_pair(p)) = *(uint32_t*)&h;
        }
    }
}

// ---------------- all-to-all grid barrier among 64 recurrence CTAs ----------------
__device__ __forceinline__ void grid_sync_aa(int t) {
    __syncthreads();
    if (threadIdx.x == 0) {
        __threadfence();
        *(volatile int*)&g_flags[blockIdx.x * 32] = t + 1;
    }
    if (threadIdx.x < NBLK_R)
        while (*(volatile int*)&g_flags[threadIdx.x * 32] <= t) { }
    __syncthreads();
}

// ---------------- fused kernel: 64 recurrence CTAs + 232 gemm workers ----------------
// 296 CTAs = exactly 2-CTA/SM capacity. Recurrence CTAs (blocks 0..63) are wave-1
// resident -> barrier-safe. Gemm workers steal (mb,nb,kz) tiles mb-ascending and
// publish per-mb completion; recurrence gates each step on the mb it needs.
__global__ void __launch_bounds__(256, 2) fused_k(const float* __restrict__ b_h) {
    __shared__ __align__(128) uint8_t sh[34816];
    __shared__ __align__(8) uint64_t s_full[2];
    __shared__ int s_tile;

    const int tid = threadIdx.x, lane = tid & 31, warp = tid >> 5;

    if (blockIdx.x >= NBLK_R) {
        // ================= GEMM worker =================
        const uint32_t mb_full[2] = { s2u(&s_full[0]), s2u(&s_full[1]) };
        if (tid == 0) { mbar_init(mb_full[0], 1); mbar_init(mb_full[1], 1); }
        const int wm = warp & 3, wn = warp >> 2, g = lane >> 2, tg = lane & 3;
        const uint32_t sa0 = s2u(sh);
        const uint32_t sb0 = s2u(sh + 2 * TILEB);
        const uint32_t a_off = (uint32_t)((wm * 32 + g) * 64 + tg * 16);
        const uint32_t b_off = (uint32_t)((wn * 64 + g) * 64 + tg * 16);
        __syncthreads();

        for (;;) {
            if (tid == 0) s_tile = atomicAdd(&g_tile, 1);
            __syncthreads();
            const int tile = s_tile;
            if (tile >= NTILES) break;
            const int mb = tile >> 4, sub = tile & 15, nb = sub & 7, kz = sub >> 3;
            const int kt0 = kz * KT_HALF;
            const uint8_t* Ab = g_Apk + (size_t)mb * KT * TILEB;
            const uint8_t* Bb = g_Bpk + (size_t)nb * KT * TILEB;

            if (tid == 0) {
                #pragma unroll
                for (int s = 0; s < 2; s++) {
                    mbar_expect(mb_full[s], 2 * TILEB);
                    bulk_g2s(sa0 + s * TILEB, Ab + (size_t)(kt0 + s) * TILEB, TILEB, mb_full[s]);
                    bulk_g2s(sb0 + s * TILEB, Bb + (size_t)(kt0 + s) * TILEB, TILEB, mb_full[s]);
                }
            }

            float acc[2][8][4];
            #pragma unroll
            for (int mi = 0; mi < 2; mi++)
                #pragma unroll
                for (int ni = 0; ni < 8; ni++)
                    #pragma unroll
                    for (int j = 0; j < 4; j++) acc[mi][ni][j] = 0.0f;

            #pragma unroll 1
            for (int it = 0; it < KT_HALF; it++) {
                const int s  = it & 1;
                const int ph = (it >> 1) & 1;
                mbar_wait(mb_full[s], ph);

                const uint8_t* As = sh + s * TILEB;
                const uint8_t* Bs = sh + 2 * TILEB + s * TILEB;

                uint4 aL0 = *(const uint4*)(As + a_off);
                uint4 aH0 = *(const uint4*)(As + a_off + 512);
                uint4 aL1 = *(const uint4*)(As + a_off + 1024);
                uint4 aH1 = *(const uint4*)(As + a_off + 1536);
                uint4 bf[8];
                #pragma unroll
                for (int ni = 0; ni < 8; ni++)
                    bf[ni] = *(const uint4*)(Bs + b_off + ni * 512);

                __syncthreads();
                const int nk = it + 2;
                if (tid == 0 && nk < KT_HALF) {
                    mbar_expect(mb_full[s], 2 * TILEB);
                    bulk_g2s(sa0 + s * TILEB, Ab + (size_t)(kt0 + nk) * TILEB, TILEB, mb_full[s]);
                    bulk_g2s(sb0 + s * TILEB, Bb + (size_t)(kt0 + nk) * TILEB, TILEB, mb_full[s]);
                }

                #pragma unroll
                for (int ni = 0; ni < 8; ni++)
                    hmma(acc[0][ni], aL0.x, aH0.x, aL0.y, aH0.y, bf[ni].x, bf[ni].y);
                #pragma unroll
                for (int ni = 0; ni < 8; ni++)
                    hmma(acc[1][ni], aL1.x, aH1.x, aL1.y, aH1.y, bf[ni].x, bf[ni].y);
                #pragma unroll
                for (int ni = 0; ni < 8; ni++)
                    hmma(acc[0][ni], aL0.z, aH0.z, aL0.w, aH0.w, bf[ni].z, bf[ni].w);
                #pragma unroll
                for (int ni = 0; ni < 8; ni++)
                    hmma(acc[1][ni], aL1.z, aH1.z, aL1.w, aH1.w, bf[ni].z, bf[ni].w);
            }

            float* Zo = (kz == 0) ? g_Z : g_Z2;
            const int cg = tg * 2;
            #pragma unroll
            for (int mi = 0; mi < 2; mi++) {
                #pragma unroll
                for (int ni = 0; ni < 8; ni++) {
                    int row = mb * 128 + wm * 32 + mi * 16 + g;
                    int col = nb * 128 + wn * 64 + ni * 8 + cg;
                    Zo[(size_t)row * HID + col]           = acc[mi][ni][0];
                    Zo[(size_t)row * HID + col + 1]       = acc[mi][ni][1];
                    Zo[(size_t)(row + 8) * HID + col]     = acc[mi][ni][2];
                    Zo[(size_t)(row + 8) * HID + col + 1] = acc[mi][ni][3];
                }
            }
            __threadfence();
            __syncthreads();
            if (tid == 0) atomicAdd(&g_mbcnt[mb], 1);
        }
        return;
    }

    // ================= tensor-core recurrence =================
    uint8_t* sW = sh;                                       // 32 KB
    float4 (*sRed)[32] = (float4(*)[32])(sh + 32768);       // 2 KB

    const int cta = blockIdx.x;
    const int mt = warp & 1, nt = (warp >> 1) & 1, ks = warp >> 2;
    const int g = lane >> 2, tg = lane & 3;

    for (int i = tid; i < 2048; i += 256)
        *(uint4*)(sW + i * 16) = *(const uint4*)(g_Wpk + (size_t)cta * 32768 + i * 16);

    const int c0 = cta * 16 + nt * 8 + 2 * tg;
    const float bias0 = b_h[c0], bias1 = b_h[c0 + 1];
    const int r0 = mt * 16 + g;
    const int r1 = r0 + 8;
    const bool v1 = (r1 < BSZ);
    const uint32_t sW_u = s2u(sW);
    __syncthreads();

    int mb_ready = -1;
    for (int t = 0; t < T_STEPS; t++) {
        // gate on gemm progress: last row needed is t*25+24 -> mb index >>7
        const int mbn = (t * 25 + 24) >> 7;
        if (mbn != mb_ready) {
            if (tid == 0)
                while (*(volatile int*)&g_mbcnt[mbn] < 16) { }
            __syncthreads();
            mb_ready = mbn;
        }

        const uint8_t* hIn  = g_hA[t & 1];
        uint8_t*       hOut = g_hA[(t + 1) & 1];

        float z00 = 0.f, z01 = 0.f, z10 = 0.f, z11 = 0.f;
        if (ks == 0) {
            const float* Z1t = g_Z  + (size_t)t * BSZ * HID;
            const float* Z2t = g_Z2 + (size_t)t * BSZ * HID;
            int i0 = r0 * HID + c0;
            float2 a = ldg_cg64f(Z1t + i0), b = ldg_cg64f(Z2t + i0);
            z00 = a.x + b.x; z01 = a.y + b.y;
            if (v1) {
                int i1 = r1 * HID + c0;
                float2 c = ldg_cg64f(Z1t + i1), d = ldg_cg64f(Z2t + i1);
                z10 = c.x + d.x; z11 = c.y + d.y;
            }
        }

        float acc0[4] = {0, 0, 0, 0}, acc1[4] = {0, 0, 0, 0};
        const int kc0 = ks * 32;
        const uint8_t* aBase = hIn + mt * 512 + lane * 16;
        uint4 ab[2][8];
        #pragma unroll
        for (int j = 0; j < 8; j++)
            ab[0][j] = ldg_cg128(aBase + (size_t)(kc0 + j) * 1024);
        #pragma unroll
        for (int v = 0; v < 4; v++) {
            const int cur = v & 1;
            if (v < 3) {
                #pragma unroll
                for (int j = 0; j < 8; j++)
                    ab[cur ^ 1][j] = ldg_cg128(aBase + (size_t)(kc0 + (v + 1) * 8 + j) * 1024);
            }
            #pragma unroll
            for (int j = 0; j < 8; j++) {
                const int kc = kc0 + v * 8 + j;
                uint32_t b0, b1;
                asm("ld.shared.v2.u32 {%0,%1}, [%2];" : "=r"(b0), "=r"(b1)
                    : "r"(sW_u + kc * 512 + nt * 256 + lane * 8));
                hmma((j & 1) ? acc1 : acc0,
                     ab[cur][j].x, ab[cur][j].y, ab[cur][j].z, ab[cur][j].w, b0, b1);
            }
        }
        float accf[4];
        #pragma unroll
        for (int q = 0; q < 4; q++) accf[q] = acc0[q] + acc1[q];

        if (ks == 1)
            sRed[warp - 4][lane] = make_float4(accf[0], accf[1], accf[2], accf[3]);
        __syncthreads();

        if (ks == 0) {
            float4 o = sRed[warp][lane];
            accf[0] += o.x; accf[1] += o.y; accf[2] += o.z; accf[3] += o.w;

            float h00 = tanhf(z00 + accf[0] + bias0);
            float h01 = tanhf(z01 + accf[1] + bias1);
            __half2 p0 = __floats2half2_rn(h00, h01);
            uint32_t* dst = (uint32_t*)(hOut + cta * 1024 + mt * 512 + (g * 4 + tg) * 16 + nt * 8);
            dst[0] = *(uint32_t*)&p0;
            if (v1) {
                float h10 = tanhf(z10 + accf[2] + bias0);
                float h11 = tanhf(z11 + accf[3] + bias1);
                __half2 p1 = __floats2half2_rn(h10, h11);
                dst[1] = *(uint32_t*)&p1;
                if (t == T_STEPS - 1) {
                    g_hfin[r1 * HID + c0]     = h10;
                    g_hfin[r1 * HID + c0 + 1] = h11;
                }
            }
            if (t == T_STEPS - 1) {
                g_hfin[r0 * HID + c0]     = h00;
                g_hfin[r0 * HID + c0 + 1] = h01;
            }
        }

        grid_sync_aa(t);
    }
}

// ---------------- pool + FC + softmax ----------------
__global__ void final_k(const float* __restrict__ fc_w,
                        const float* __restrict__ fc_b,
                        float* __restrict__ out) {
    __shared__ float s0[256], s1[256];
    int tid = threadIdx.x;
    float l0 = 0.0f, l1 = 0.0f;
    for (int j = tid; j < HID; j += 256) {
        float p = 0.0f;
        #pragma unroll
        for (int rr = 0; rr < BSZ; rr++) p += g_hfin[rr * HID + j];
        p *= (1.0f / (float)BSZ);
        l0 += p * fc_w[j * NCLS + 0];
        l1 += p * fc_w[j * NCLS + 1];
    }
    s0[tid] = l0; s1[tid] = l1;
    __syncthreads();
    for (int s = 128; s; s >>= 1) {
        if (tid < s) { s0[tid] += s0[tid + s]; s1[tid] += s1[tid + s]; }
        __syncthreads();
    }
    if (tid == 0) {
        float a = s0[0] + fc_b[0];
        float b = s1[0] + fc_b[1];
        float m = fmaxf(a, b);
        float e0 = expf(a - m), e1 = expf(b - m);
        float inv = 1.0f / (e0 + e1);
        out[0] = e0 * inv;
        out[1] = e1 * inv;
    }
}

// ---------------- launch ----------------
extern "C" void kernel_launch(void* const* d_in, const int* in_sizes, int n_in,
                              void* d_out, int out_size) {
    const float* X   = (const float*)d_in[0];
    const float* Wxh = (const float*)d_in[1];
    const float* Whh = (const float*)d_in[2];
    const float* bh  = (const float*)d_in[3];
    const float* fcw = (const float*)d_in[4];
    const float* fcb = (const float*)d_in[5];
    float* out = (float*)d_out;

    init_k<<<100, 256>>>();                          // 1
    packW<<<NBLK_R, 256>>>(Whh);                     // 2
    pack_all<<<dim3(KT, 58), 256>>>(X, Wxh);         // 3
    fused_k<<<NBLK_R + NBLK_G, 256>>>(bh);           // 4  <- ncu capture slot
    final_k<<<1, 256>>>(fcw, fcb, out);              // 5
}